// round 15
// baseline (speedup 1.0000x reference)
#include <cuda_runtime.h>
#include <cuda_fp16.h>
#include <cstdint>

// GraphConv: out = segment_sum(x[src], dst, N) @ W2 + b2
// Pipeline: prep (detect + W2 bf16-split frags) -> conv (x->fp16) ->
//           fill (bucket sort) -> gather (warp/node fp16 rows, READ-ONLY g_cnt)
//           -> persistent 3xBF16 mma GEMM (B staged once; zeroes g_cnt/g_ovf_cnt)

constexpr int NN = 50000;
constexpr int FD = 128;
constexpr int NE = 600000;
constexpr int CAP = 64;
constexpr int OVF_CAP = 8192;
constexpr int TILES = (NN + 127) / 128;   // 391
constexpr int GCTAS = 148;

__device__ int g_cnt[NN];                  // zero at load; zeroed by gemm each run
__device__ int g_adj[(size_t)NN * CAP];
__device__ int g_ovf[OVF_CAP * 2];
__device__ int g_ovf_cnt;                  // reset by gemm block 0
__device__ int g_idx64;
__device__ __align__(16) uint32_t g_xh[(size_t)NN * 64];   // x rows as half2
__device__ __align__(16) uint32_t g_Ah[(size_t)NN * 64];   // agg bf16 hi plane
__device__ __align__(16) uint32_t g_Al[(size_t)NN * 64];   // agg bf16 lo plane
__device__ __align__(16) uint4 g_Bfrag[8 * 16 * 32];       // W2 frags {bh0,bh1,bl0,bl1}

// ---------------------------------------------------------------------------
__device__ __forceinline__ uint32_t pack_bf16(float lo, float hi) {
    uint32_t r;
    asm("cvt.rn.bf16x2.f32 %0, %1, %2;" : "=r"(r) : "f"(hi), "f"(lo));
    return r;
}
__device__ __forceinline__ float bf_lo(uint32_t u) { return __uint_as_float(u << 16); }
__device__ __forceinline__ float bf_hi(uint32_t u) { return __uint_as_float(u & 0xFFFF0000u); }
__device__ __forceinline__ void split2(float f0, float f1, uint32_t& h, uint32_t& l) {
    h = pack_bf16(f0, f1);
    l = pack_bf16(f0 - bf_lo(h), f1 - bf_hi(h));
}

// ---------------------------------------------------------------------------
// prep: block 0 detect idx dtype; blocks [1,17) build Bfrag.
// ---------------------------------------------------------------------------
__global__ void prep_kernel(const unsigned int* __restrict__ w,
                            const float* __restrict__ W2) {
    if (blockIdx.x == 0) {
        __shared__ int found;
        if (threadIdx.x == 0) found = 0;
        __syncthreads();
        unsigned int v = 0;
        for (int j = threadIdx.x; j < 1024; j += 256) v |= w[2 * j + 1];
        if (v) atomicOr(&found, 1);
        __syncthreads();
        if (threadIdx.x == 0) g_idx64 = found ? 0 : 1;
    } else {
        int i = (blockIdx.x - 1) * 256 + threadIdx.x;   // 0..4095
        int lane = i & 31, nt = (i >> 5) & 15, ks = i >> 9;
        int g = lane >> 2, t = lane & 3;
        int n = nt * 8 + g, k0 = ks * 16;
        float v00 = W2[(k0 + 2 * t) * FD + n];
        float v01 = W2[(k0 + 2 * t + 1) * FD + n];
        float v10 = W2[(k0 + 2 * t + 8) * FD + n];
        float v11 = W2[(k0 + 2 * t + 9) * FD + n];
        uint4 f;
        split2(v00, v01, f.x, f.z);
        split2(v10, v11, f.y, f.w);
        g_Bfrag[i] = f;
    }
}

// ---------------------------------------------------------------------------
// conv: x (fp32) -> g_xh (fp16 half2 words).
// ---------------------------------------------------------------------------
__global__ void conv_kernel(const float* __restrict__ x) {
    const int total = NN * 16;                 // uint4 outputs
    int stride = gridDim.x * blockDim.x;
    const float4* xg = reinterpret_cast<const float4*>(x);
    uint4* og = reinterpret_cast<uint4*>(g_xh);
    for (int i = blockIdx.x * blockDim.x + threadIdx.x; i < total; i += stride) {
        float4 v0 = xg[2 * i];
        float4 v1 = xg[2 * i + 1];
        __half2 h0 = __float22half2_rn(make_float2(v0.x, v0.y));
        __half2 h1 = __float22half2_rn(make_float2(v0.z, v0.w));
        __half2 h2 = __float22half2_rn(make_float2(v1.x, v1.y));
        __half2 h3 = __float22half2_rn(make_float2(v1.z, v1.w));
        uint4 o;
        o.x = *reinterpret_cast<uint32_t*>(&h0);
        o.y = *reinterpret_cast<uint32_t*>(&h1);
        o.z = *reinterpret_cast<uint32_t*>(&h2);
        o.w = *reinterpret_cast<uint32_t*>(&h3);
        og[i] = o;
    }
}

// ---------------------------------------------------------------------------
__global__ void fill_kernel(const void* __restrict__ ei_raw) {
    int e = blockIdx.x * blockDim.x + threadIdx.x;
    if (e >= NE) return;
    int src, dst;
    if (g_idx64) {
        const long long* ei = reinterpret_cast<const long long*>(ei_raw);
        src = (int)ei[e];
        dst = (int)ei[NE + e];
    } else {
        const int* ei = reinterpret_cast<const int*>(ei_raw);
        src = ei[e];
        dst = ei[NE + e];
    }
    int p = atomicAdd(&g_cnt[dst], 1);
    if (p < CAP) {
        g_adj[dst * CAP + p] = src;
    } else {
        int q = atomicAdd(&g_ovf_cnt, 1);
        if (q < OVF_CAP) { g_ovf[2 * q] = src; g_ovf[2 * q + 1] = dst; }
    }
}

// ---------------------------------------------------------------------------
// Gather: warp/node over fp16 rows (uint2 per lane); fp32 accumulate;
// emits bf16 hi/lo planes. g_cnt is READ-ONLY here (zeroed later by gemm).
// ---------------------------------------------------------------------------
__device__ __forceinline__ void acc_u2(float4& acc, uint32_t wx, uint32_t wy) {
    float2 f0 = __half22float2(*reinterpret_cast<__half2*>(&wx));
    float2 f1 = __half22float2(*reinterpret_cast<__half2*>(&wy));
    acc.x += f0.x; acc.y += f0.y; acc.z += f1.x; acc.w += f1.y;
}

__global__ __launch_bounds__(128) void gather_kernel() {
    int n = blockIdx.x * 4 + (threadIdx.x >> 5);
    if (n >= NN) return;
    int lane = threadIdx.x & 31;

    int deg = g_cnt[n];
    const int* adjp = g_adj + (size_t)n * CAP;
    int a0 = adjp[lane];
    int a1 = adjp[lane + 32];

    float4 acc = make_float4(0.f, 0.f, 0.f, 0.f);
    const uint2* xh = reinterpret_cast<const uint2*>(g_xh);

    if (deg > CAP) {            // rare overflow tail
        int cnt = g_ovf_cnt;
        if (cnt > OVF_CAP) cnt = OVF_CAP;
        for (int q = 0; q < cnt; q++) {
            if (g_ovf[2 * q + 1] == n) {
                int s = g_ovf[2 * q];
                uint2 v = xh[(size_t)s * 32 + lane];
                acc_u2(acc, v.x, v.y);
            }
        }
        deg = CAP;
    }

    int j = 0;
    for (; j + 4 <= deg; j += 4) {
        int base = (j < 32) ? a0 : a1;
        int s0 = __shfl_sync(0xffffffffu, base, (j + 0) & 31);
        int s1 = __shfl_sync(0xffffffffu, base, (j + 1) & 31);
        int s2 = __shfl_sync(0xffffffffu, base, (j + 2) & 31);
        int s3 = __shfl_sync(0xffffffffu, base, (j + 3) & 31);
        uint2 v0 = xh[(size_t)s0 * 32 + lane];
        uint2 v1 = xh[(size_t)s1 * 32 + lane];
        uint2 v2 = xh[(size_t)s2 * 32 + lane];
        uint2 v3 = xh[(size_t)s3 * 32 + lane];
        acc_u2(acc, v0.x, v0.y);
        acc_u2(acc, v1.x, v1.y);
        acc_u2(acc, v2.x, v2.y);
        acc_u2(acc, v3.x, v3.y);
    }
    for (; j < deg; j++) {
        int base = (j < 32) ? a0 : a1;
        int s = __shfl_sync(0xffffffffu, base, j & 31);
        uint2 v = xh[(size_t)s * 32 + lane];
        acc_u2(acc, v.x, v.y);
    }

    uint32_t h0, l0, h1, l1;
    split2(acc.x, acc.y, h0, l0);
    split2(acc.z, acc.w, h1, l1);
    *reinterpret_cast<uint2*>(g_Ah + (size_t)n * 64 + lane * 2) = make_uint2(h0, h1);
    *reinterpret_cast<uint2*>(g_Al + (size_t)n * 64 + lane * 2) = make_uint2(l0, l1);
}

// ---------------------------------------------------------------------------
// Persistent 3xBF16 GEMM: 148 CTAs x 512 threads. B fragment table + bias
// staged once per CTA; tiles bid, bid+148, bid+296 processed in a loop
// (constant work per tile -> static partition is balanced).
// warp w: rows (w&7)*16..+16, col half (w>>3)*64 of the current tile.
// Zeroes each tile's g_cnt rows + g_ovf_cnt for the next replay.
// ---------------------------------------------------------------------------
constexpr int LDAB = 272;
constexpr int SM_AL = 128 * LDAB;
constexpr int SM_BF = 2 * 128 * LDAB;
constexpr int SM_BIAS = SM_BF + 65536;
constexpr int GEMM_SMEM = SM_BIAS + 512;   // 135680

__device__ __forceinline__ void mma16(float* c, uint32_t a0, uint32_t a1, uint32_t a2,
                                      uint32_t a3, uint32_t b0, uint32_t b1) {
    asm volatile(
        "mma.sync.aligned.m16n8k16.row.col.f32.bf16.bf16.f32 "
        "{%0,%1,%2,%3}, {%4,%5,%6,%7}, {%8,%9}, {%0,%1,%2,%3};"
        : "+f"(c[0]), "+f"(c[1]), "+f"(c[2]), "+f"(c[3])
        : "r"(a0), "r"(a1), "r"(a2), "r"(a3), "r"(b0), "r"(b1));
}

__global__ __launch_bounds__(512, 1) void gemm_kernel(const float* __restrict__ b2,
                                                      float* __restrict__ out) {
    extern __shared__ char smem[];
    int tid = threadIdx.x;

    if (blockIdx.x == 0 && tid == 0) g_ovf_cnt = 0;   // reset for next replay

    // Stage B fragment table + bias ONCE
    {
        uint4* bs = reinterpret_cast<uint4*>(smem + SM_BF);
#pragma unroll
        for (int it = 0; it < 8; it++) bs[tid + it * 512] = g_Bfrag[tid + it * 512];
    }
    if (tid < FD) reinterpret_cast<float*>(smem + SM_BIAS)[tid] = b2[tid];

    int wid = tid >> 5;
    int lane = tid & 31;
    int g = lane >> 2;
    int t = lane & 3;
    int w8 = wid & 7;
    int h = wid >> 3;

    const char* Ah_base = smem + (w8 * 16 + g) * LDAB + 4 * t;
    const char* Al_base = Ah_base + SM_AL;
    const float* bias = reinterpret_cast<const float*>(smem + SM_BIAS);

    for (int tile = blockIdx.x; tile < TILES; tile += GCTAS) {
        int row0 = tile * 128;

        // zero this tile's g_cnt rows for the next replay
        if (tid < 128 && row0 + tid < NN) g_cnt[row0 + tid] = 0;

        __syncthreads();   // prior iteration's mma reads done; B staged (1st iter)

        // Stage A hi/lo planes for this tile
        {
            const uint4* ahg = reinterpret_cast<const uint4*>(g_Ah);
            const uint4* alg = reinterpret_cast<const uint4*>(g_Al);
#pragma unroll
            for (int it = 0; it < 4; it++) {
                int idx = tid + it * 512;            // 0..2047
                int r = idx >> 4, cg = idx & 15;
                uint4 zv = make_uint4(0, 0, 0, 0);
                uint4 hv = zv, lv = zv;
                if (row0 + r < NN) {
                    hv = ahg[(size_t)(row0 + r) * 16 + cg];
                    lv = alg[(size_t)(row0 + r) * 16 + cg];
                }
                *reinterpret_cast<uint4*>(smem + r * LDAB + cg * 16) = hv;
                *reinterpret_cast<uint4*>(smem + SM_AL + r * LDAB + cg * 16) = lv;
            }
        }
        __syncthreads();

        float acc[8][4];
#pragma unroll
        for (int i = 0; i < 8; i++)
#pragma unroll
            for (int j = 0; j < 4; j++) acc[i][j] = 0.f;

#pragma unroll
        for (int ks = 0; ks < 8; ks++) {
            int ko = ks * 32;
            uint32_t ah0 = *reinterpret_cast<const uint32_t*>(Ah_base + ko);
            uint32_t ah1 = *reinterpret_cast<const uint32_t*>(Ah_base + ko + 8 * LDAB);
            uint32_t ah2 = *reinterpret_cast<const uint32_t*>(Ah_base + ko + 16);
            uint32_t ah3 = *reinterpret_cast<const uint32_t*>(Ah_base + ko + 8 * LDAB + 16);
            uint32_t al0 = *reinterpret_cast<const uint32_t*>(Al_base + ko);
            uint32_t al1 = *reinterpret_cast<const uint32_t*>(Al_base + ko + 8 * LDAB);
            uint32_t al2 = *reinterpret_cast<const uint32_t*>(Al_base + ko + 16);
            uint32_t al3 = *reinterpret_cast<const uint32_t*>(Al_base + ko + 8 * LDAB + 16);

            const uint4* Bf = reinterpret_cast<const uint4*>(smem + SM_BF)
                              + ks * 512 + h * 256 + lane;
#pragma unroll
            for (int nt = 0; nt < 8; nt++) {
                uint4 b = Bf[nt * 32];
                mma16(acc[nt], ah0, ah1, ah2, ah3, b.x, b.y);   // ah*bh
                mma16(acc[nt], al0, al1, al2, al3, b.x, b.y);   // al*bh
                mma16(acc[nt], ah0, ah1, ah2, ah3, b.z, b.w);   // ah*bl
            }
        }

        int rA = row0 + w8 * 16 + g;
        int rB = rA + 8;
#pragma unroll
        for (int nt = 0; nt < 8; nt++) {
            int col = (h * 8 + nt) * 8 + 2 * t;
            float bx = bias[col], by = bias[col + 1];
            if (rA < NN) {
                float2 v = make_float2(acc[nt][0] + bx, acc[nt][1] + by);
                *reinterpret_cast<float2*>(out + (size_t)rA * FD + col) = v;
            }
            if (rB < NN) {
                float2 v = make_float2(acc[nt][2] + bx, acc[nt][3] + by);
                *reinterpret_cast<float2*>(out + (size_t)rB * FD + col) = v;
            }
        }
    }
}

// ---------------------------------------------------------------------------
extern "C" void kernel_launch(void* const* d_in, const int* in_sizes, int n_in,
                              void* d_out, int out_size) {
    const float* x  = (const float*)d_in[0];
    const void*  ei = d_in[1];
    // d_in[2]=edge_weight, d_in[3]=W1, d_in[4]=b1 : dead in reference
    const float* W2 = (const float*)d_in[5];
    const float* b2 = (const float*)d_in[6];
    float* out = (float*)d_out;

    cudaFuncSetAttribute(gemm_kernel, cudaFuncAttributeMaxDynamicSharedMemorySize, GEMM_SMEM);

    prep_kernel<<<17, 256>>>((const unsigned int*)ei, W2);
    conv_kernel<<<784, 256>>>(x);
    fill_kernel<<<(NE + 255) / 256, 256>>>(ei);
    gather_kernel<<<(NN + 3) / 4, 128>>>();
    gemm_kernel<<<GCTAS, 512, GEMM_SMEM>>>(b2, out);
}

// round 16
// speedup vs baseline: 1.1141x; 1.1141x over previous
#include <cuda_runtime.h>
#include <cstdint>

// GraphConv: out = segment_sum(x[src], dst, N) @ W2 + b2
// Pipeline: prep (detect + W2 bf16-split frags) -> fill (bucket sort) ->
//           gather (warp/node fp32 float4, READ-ONLY g_cnt, emits bf16 planes)
//           -> persistent 3xBF16 mma GEMM with cp.async double-buffered A
//              (B staged once; zeroes g_cnt tiles + g_ovf_cnt for next replay)

constexpr int NN = 50000;
constexpr int FD = 128;
constexpr int NE = 600000;
constexpr int CAP = 64;
constexpr int OVF_CAP = 8192;
constexpr int TILES = (NN + 127) / 128;   // 391
constexpr int GCTAS = 148;
constexpr int AROWS = TILES * 128;        // padded row count (50048)

__device__ int g_cnt[NN];                  // zero at load; zeroed by gemm each run
__device__ int g_adj[(size_t)NN * CAP];
__device__ int g_ovf[OVF_CAP * 2];
__device__ int g_ovf_cnt;                  // reset by gemm block 0
__device__ int g_idx64;
__device__ __align__(16) uint32_t g_Ah[(size_t)AROWS * 64];  // agg bf16 hi plane
__device__ __align__(16) uint32_t g_Al[(size_t)AROWS * 64];  // agg bf16 lo plane
__device__ __align__(16) uint4 g_Bfrag[8 * 16 * 32];         // W2 frags {bh0,bh1,bl0,bl1}

// ---------------------------------------------------------------------------
__device__ __forceinline__ uint32_t pack_bf16(float lo, float hi) {
    uint32_t r;
    asm("cvt.rn.bf16x2.f32 %0, %1, %2;" : "=r"(r) : "f"(hi), "f"(lo));
    return r;
}
__device__ __forceinline__ float bf_lo(uint32_t u) { return __uint_as_float(u << 16); }
__device__ __forceinline__ float bf_hi(uint32_t u) { return __uint_as_float(u & 0xFFFF0000u); }
__device__ __forceinline__ void split2(float f0, float f1, uint32_t& h, uint32_t& l) {
    h = pack_bf16(f0, f1);
    l = pack_bf16(f0 - bf_lo(h), f1 - bf_hi(h));
}
__device__ __forceinline__ uint32_t smem_u32(const void* p) {
    uint32_t a;
    asm("{ .reg .u64 t; cvta.to.shared.u64 t, %1; cvt.u32.u64 %0, t; }" : "=r"(a) : "l"(p));
    return a;
}

// ---------------------------------------------------------------------------
// prep: block 0 detect idx dtype; blocks [1,17) build Bfrag.
// ---------------------------------------------------------------------------
__global__ void prep_kernel(const unsigned int* __restrict__ w,
                            const float* __restrict__ W2) {
    if (blockIdx.x == 0) {
        __shared__ int found;
        if (threadIdx.x == 0) found = 0;
        __syncthreads();
        unsigned int v = 0;
        for (int j = threadIdx.x; j < 1024; j += 256) v |= w[2 * j + 1];
        if (v) atomicOr(&found, 1);
        __syncthreads();
        if (threadIdx.x == 0) g_idx64 = found ? 0 : 1;
    } else {
        int i = (blockIdx.x - 1) * 256 + threadIdx.x;   // 0..4095
        int lane = i & 31, nt = (i >> 5) & 15, ks = i >> 9;
        int g = lane >> 2, t = lane & 3;
        int n = nt * 8 + g, k0 = ks * 16;
        float v00 = W2[(k0 + 2 * t) * FD + n];
        float v01 = W2[(k0 + 2 * t + 1) * FD + n];
        float v10 = W2[(k0 + 2 * t + 8) * FD + n];
        float v11 = W2[(k0 + 2 * t + 9) * FD + n];
        uint4 f;
        split2(v00, v01, f.x, f.z);
        split2(v10, v11, f.y, f.w);
        g_Bfrag[i] = f;
    }
}

// ---------------------------------------------------------------------------
__global__ void fill_kernel(const void* __restrict__ ei_raw) {
    int e = blockIdx.x * blockDim.x + threadIdx.x;
    if (e >= NE) return;
    int src, dst;
    if (g_idx64) {
        const long long* ei = reinterpret_cast<const long long*>(ei_raw);
        src = (int)ei[e];
        dst = (int)ei[NE + e];
    } else {
        const int* ei = reinterpret_cast<const int*>(ei_raw);
        src = ei[e];
        dst = ei[NE + e];
    }
    int p = atomicAdd(&g_cnt[dst], 1);
    if (p < CAP) {
        g_adj[dst * CAP + p] = src;
    } else {
        int q = atomicAdd(&g_ovf_cnt, 1);
        if (q < OVF_CAP) { g_ovf[2 * q] = src; g_ovf[2 * q + 1] = dst; }
    }
}

// ---------------------------------------------------------------------------
// Gather: warp/node over fp32 rows (float4 per lane); exact fp32 accumulate;
// emits bf16 hi/lo planes. g_cnt is READ-ONLY here (zeroed later by gemm).
// ---------------------------------------------------------------------------
__global__ __launch_bounds__(128) void gather_kernel(const float* __restrict__ x) {
    int n = blockIdx.x * 4 + (threadIdx.x >> 5);
    if (n >= NN) return;
    int lane = threadIdx.x & 31;

    int deg = g_cnt[n];
    const int* adjp = g_adj + (size_t)n * CAP;
    int a0 = adjp[lane];
    int a1 = adjp[lane + 32];

    float4 acc = make_float4(0.f, 0.f, 0.f, 0.f);

    if (deg > CAP) {            // rare overflow tail
        int cnt = g_ovf_cnt;
        if (cnt > OVF_CAP) cnt = OVF_CAP;
        for (int q = 0; q < cnt; q++) {
            if (g_ovf[2 * q + 1] == n) {
                int s = g_ovf[2 * q];
                float4 v = *(reinterpret_cast<const float4*>(x + (size_t)s * FD) + lane);
                acc.x += v.x; acc.y += v.y; acc.z += v.z; acc.w += v.w;
            }
        }
        deg = CAP;
    }

    int j = 0;
    for (; j + 4 <= deg; j += 4) {
        int base = (j < 32) ? a0 : a1;
        int s0 = __shfl_sync(0xffffffffu, base, (j + 0) & 31);
        int s1 = __shfl_sync(0xffffffffu, base, (j + 1) & 31);
        int s2 = __shfl_sync(0xffffffffu, base, (j + 2) & 31);
        int s3 = __shfl_sync(0xffffffffu, base, (j + 3) & 31);
        float4 v0 = *(reinterpret_cast<const float4*>(x + (size_t)s0 * FD) + lane);
        float4 v1 = *(reinterpret_cast<const float4*>(x + (size_t)s1 * FD) + lane);
        float4 v2 = *(reinterpret_cast<const float4*>(x + (size_t)s2 * FD) + lane);
        float4 v3 = *(reinterpret_cast<const float4*>(x + (size_t)s3 * FD) + lane);
        acc.x += v0.x + v1.x + v2.x + v3.x;
        acc.y += v0.y + v1.y + v2.y + v3.y;
        acc.z += v0.z + v1.z + v2.z + v3.z;
        acc.w += v0.w + v1.w + v2.w + v3.w;
    }
    for (; j < deg; j++) {
        int base = (j < 32) ? a0 : a1;
        int s = __shfl_sync(0xffffffffu, base, j & 31);
        float4 v = *(reinterpret_cast<const float4*>(x + (size_t)s * FD) + lane);
        acc.x += v.x; acc.y += v.y; acc.z += v.z; acc.w += v.w;
    }

    uint32_t h0, l0, h1, l1;
    split2(acc.x, acc.y, h0, l0);
    split2(acc.z, acc.w, h1, l1);
    *reinterpret_cast<uint2*>(g_Ah + (size_t)n * 64 + lane * 2) = make_uint2(h0, h1);
    *reinterpret_cast<uint2*>(g_Al + (size_t)n * 64 + lane * 2) = make_uint2(l0, l1);
}

// ---------------------------------------------------------------------------
// Persistent 3xBF16 GEMM: 148 CTAs x 512 threads, cp.async double-buffered A.
// smem: A buffers [0, 2*2*ABUF) = {buf0: Ah,Al}{buf1: Ah,Al}; B; bias.
// warp w: rows (w&7)*16..+16, col half (w>>3)*64 of the current tile.
// ---------------------------------------------------------------------------
constexpr int LDAB = 272;
constexpr int ABUF = 128 * LDAB;            // 34816 per plane
constexpr int SM_BF = 4 * ABUF;             // 139264
constexpr int SM_BIAS = SM_BF + 65536;      // 204800
constexpr int GEMM_SMEM = SM_BIAS + 512;    // 205312

__device__ __forceinline__ void mma16(float* c, uint32_t a0, uint32_t a1, uint32_t a2,
                                      uint32_t a3, uint32_t b0, uint32_t b1) {
    asm volatile(
        "mma.sync.aligned.m16n8k16.row.col.f32.bf16.bf16.f32 "
        "{%0,%1,%2,%3}, {%4,%5,%6,%7}, {%8,%9}, {%0,%1,%2,%3};"
        : "+f"(c[0]), "+f"(c[1]), "+f"(c[2]), "+f"(c[3])
        : "r"(a0), "r"(a1), "r"(a2), "r"(a3), "r"(b0), "r"(b1));
}

__global__ __launch_bounds__(512, 1) void gemm_kernel(const float* __restrict__ b2,
                                                      float* __restrict__ out) {
    extern __shared__ char smem[];
    int tid = threadIdx.x;
    uint32_t sbase = smem_u32(smem);

    if (blockIdx.x == 0 && tid == 0) g_ovf_cnt = 0;   // reset for next replay

    // Stage B fragment table + bias ONCE
    {
        uint4* bs = reinterpret_cast<uint4*>(smem + SM_BF);
#pragma unroll
        for (int it = 0; it < 8; it++) bs[tid + it * 512] = g_Bfrag[tid + it * 512];
    }
    if (tid < FD) reinterpret_cast<float*>(smem + SM_BIAS)[tid] = b2[tid];

    // cp.async stage of one tile's A planes into buffer `buf`
    auto stageA = [&](int buf, int tile) {
        const uint32_t* srcH = g_Ah + (size_t)tile * 8192;
        const uint32_t* srcL = g_Al + (size_t)tile * 8192;
        uint32_t dbase = sbase + buf * 2 * ABUF;
#pragma unroll
        for (int it = 0; it < 4; it++) {
            int idx = tid + it * 512;            // 0..2047 (16B chunks)
            int r = idx >> 4, cg = idx & 15;
            uint32_t doff = dbase + r * LDAB + cg * 16;
            asm volatile("cp.async.cg.shared.global [%0], [%1], 16;"
                         :: "r"(doff), "l"(srcH + idx * 4) : "memory");
            asm volatile("cp.async.cg.shared.global [%0], [%1], 16;"
                         :: "r"(doff + ABUF), "l"(srcL + idx * 4) : "memory");
        }
    };

    int wid = tid >> 5;
    int lane = tid & 31;
    int g = lane >> 2;
    int t = lane & 3;
    int w8 = wid & 7;
    int h = wid >> 3;
    const float* bias = reinterpret_cast<const float*>(smem + SM_BIAS);

    // prologue: stage first tile
    stageA(0, blockIdx.x);
    asm volatile("cp.async.commit_group;" ::: "memory");

    int c = 0;
    for (int tile = blockIdx.x; tile < TILES; tile += GCTAS, c ^= 1) {
        int row0 = tile * 128;

        // zero this tile's g_cnt rows for the next replay (independent)
        if (tid < 128 && row0 + tid < NN) g_cnt[row0 + tid] = 0;

        __syncthreads();   // all warps done reading the buffer we stage into next

        int nxt = tile + GCTAS;
        if (nxt < TILES) {
            stageA(c ^ 1, nxt);
            asm volatile("cp.async.commit_group;" ::: "memory");
            asm volatile("cp.async.wait_group 1;" ::: "memory");
        } else {
            asm volatile("cp.async.wait_group 0;" ::: "memory");
        }
        __syncthreads();   // current buffer's data visible to all warps

        const char* Ah_base = smem + c * 2 * ABUF + (w8 * 16 + g) * LDAB + 4 * t;
        const char* Al_base = Ah_base + ABUF;

        float acc[8][4];
#pragma unroll
        for (int i = 0; i < 8; i++)
#pragma unroll
            for (int j = 0; j < 4; j++) acc[i][j] = 0.f;

#pragma unroll
        for (int ks = 0; ks < 8; ks++) {
            int ko = ks * 32;
            uint32_t ah0 = *reinterpret_cast<const uint32_t*>(Ah_base + ko);
            uint32_t ah1 = *reinterpret_cast<const uint32_t*>(Ah_base + ko + 8 * LDAB);
            uint32_t ah2 = *reinterpret_cast<const uint32_t*>(Ah_base + ko + 16);
            uint32_t ah3 = *reinterpret_cast<const uint32_t*>(Ah_base + ko + 8 * LDAB + 16);
            uint32_t al0 = *reinterpret_cast<const uint32_t*>(Al_base + ko);
            uint32_t al1 = *reinterpret_cast<const uint32_t*>(Al_base + ko + 8 * LDAB);
            uint32_t al2 = *reinterpret_cast<const uint32_t*>(Al_base + ko + 16);
            uint32_t al3 = *reinterpret_cast<const uint32_t*>(Al_base + ko + 8 * LDAB + 16);

            const uint4* Bf = reinterpret_cast<const uint4*>(smem + SM_BF)
                              + ks * 512 + h * 256 + lane;
#pragma unroll
            for (int nt = 0; nt < 8; nt++) {
                uint4 b = Bf[nt * 32];
                mma16(acc[nt], ah0, ah1, ah2, ah3, b.x, b.y);   // ah*bh
                mma16(acc[nt], al0, al1, al2, al3, b.x, b.y);   // al*bh
                mma16(acc[nt], ah0, ah1, ah2, ah3, b.z, b.w);   // ah*bl
            }
        }

        int rA = row0 + w8 * 16 + g;
        int rB = rA + 8;
#pragma unroll
        for (int nt = 0; nt < 8; nt++) {
            int col = (h * 8 + nt) * 8 + 2 * t;
            float bx = bias[col], by = bias[col + 1];
            if (rA < NN) {
                float2 v = make_float2(acc[nt][0] + bx, acc[nt][1] + by);
                *reinterpret_cast<float2*>(out + (size_t)rA * FD + col) = v;
            }
            if (rB < NN) {
                float2 v = make_float2(acc[nt][2] + bx, acc[nt][3] + by);
                *reinterpret_cast<float2*>(out + (size_t)rB * FD + col) = v;
            }
        }
    }
}

// ---------------------------------------------------------------------------
extern "C" void kernel_launch(void* const* d_in, const int* in_sizes, int n_in,
                              void* d_out, int out_size) {
    const float* x  = (const float*)d_in[0];
    const void*  ei = d_in[1];
    // d_in[2]=edge_weight, d_in[3]=W1, d_in[4]=b1 : dead in reference
    const float* W2 = (const float*)d_in[5];
    const float* b2 = (const float*)d_in[6];
    float* out = (float*)d_out;

    cudaFuncSetAttribute(gemm_kernel, cudaFuncAttributeMaxDynamicSharedMemorySize, GEMM_SMEM);

    prep_kernel<<<17, 256>>>((const unsigned int*)ei, W2);
    fill_kernel<<<(NE + 255) / 256, 256>>>(ei);
    gather_kernel<<<(NN + 3) / 4, 128>>>(x);
    gemm_kernel<<<GCTAS, 512, GEMM_SMEM>>>(b2, out);
}